// round 8
// baseline (speedup 1.0000x reference)
#include <cuda_runtime.h>

#define BQ 128
#define SQ 512
#define NQ 10
#define NST 1024
#define TPB 512
#define AMPS 2
#define NWARP 16
#define PI_F 3.14159265358979f

typedef unsigned long long u64;

// scratch (no allocations allowed)
__device__ float g_dta[BQ*SQ*NQ];
__device__ float g_C[BQ*SQ*NQ];

__device__ __forceinline__ float2 cmul(float2 a, float2 b){
  return make_float2(a.x*b.x - a.y*b.y, a.x*b.y + a.y*b.x);
}

// ---- packed f32x2 helpers (Blackwell FFMA2 via PTX); carrier = u64 ----------
__device__ __forceinline__ u64 pk2(float x, float y){
  u64 d; asm("mov.b64 %0,{%1,%2};" : "=l"(d) : "f"(x), "f"(y)); return d;
}
__device__ __forceinline__ float2 up2(u64 d){
  float2 f; asm("mov.b64 {%0,%1},%2;" : "=f"(f.x), "=f"(f.y) : "l"(d)); return f;
}
__device__ __forceinline__ u64 fma2d(u64 a, u64 b, u64 c){
  u64 r; asm("fma.rn.f32x2 %0,%1,%2,%3;" : "=l"(r) : "l"(a), "l"(b), "l"(c)); return r;
}
__device__ __forceinline__ u64 mul2d(u64 a, u64 b){
  u64 r; asm("mul.rn.f32x2 %0,%1,%2;" : "=l"(r) : "l"(a), "l"(b)); return r;
}
// (P,Q) dual-accumulator -> packed complex: re = P.lo - Q.hi, im = P.hi + Q.lo
__device__ __forceinline__ u64 fixPQ(u64 P, u64 Q){
  float2 p = up2(P), q = up2(Q);
  return pk2(p.x - q.y, p.y + q.x);
}

// verified QSVT gather map
__device__ __forceinline__ int gmap(int a){
  int v = a;
  v ^= (v & 1) << 9;
#pragma unroll
  for (int i = 8; i >= 0; --i) v ^= ((v >> (9-i)) & 1) << (8-i);
  return v;
}

// ---------------------------------------------------------------------------
__global__ void prep_kernel(const float* __restrict__ angles,
                            const float* __restrict__ W_x,
                            const float* __restrict__ W_dt,
                            const float* __restrict__ b_dt)
{
  int idx = blockIdx.x*blockDim.x + threadIdx.x;
  if (idx >= BQ*SQ) return;
  float a[NQ];
#pragma unroll
  for (int n=0;n<NQ;n++) a[n] = angles[idx*NQ + n];
  float dtr[5];
#pragma unroll
  for (int r=0;r<5;r++){
    float s = 0.f;
#pragma unroll
    for (int n=0;n<NQ;n++) s += a[n]*W_x[r*NQ+n];
    dtr[r]=s;
  }
#pragma unroll
  for (int k=0;k<NQ;k++){
    float s=0.f;
#pragma unroll
    for (int n=0;n<NQ;n++) s += a[n]*W_x[(15+k)*NQ+n];
    g_C[idx*NQ+k]=s;
  }
#pragma unroll
  for (int n=0;n<NQ;n++){
    float s = b_dt[n];
#pragma unroll
    for (int r=0;r<5;r++) s += dtr[r]*W_dt[n*5+r];
    float sp = fmaxf(s, 0.f) + log1pf(expf(-fabsf(s)));
    g_dta[idx*NQ+n] = tanhf(sp)*PI_F;
  }
}

// complex shuffle gate on lane bit q
__device__ __forceinline__ void shflCp(u64* v, const u64* Cq, int q){
  u64 csx=Cq[0], csy=Cq[1], cpx=Cq[2], cpy=Cq[3];
#pragma unroll
  for (int m=0;m<AMPS;m++){
    u64 p = __shfl_xor_sync(0xffffffffu, v[m], 1<<q);
    u64 P = fma2d(cpx, p, mul2d(csx, v[m]));
    u64 Q = fma2d(cpy, p, mul2d(csy, v[m]));
    v[m] = fixPQ(P, Q);
  }
}

// real (RY) shuffle gate on lane bit q
__device__ __forceinline__ void shflRp(u64* v, float c, float s, int q, int lane){
  float sp = ((lane >> q) & 1) ? s : -s;
  u64 c2 = pk2(c, c), sp2 = pk2(sp, sp);
#pragma unroll
  for (int m=0;m<AMPS;m++){
    u64 p = __shfl_xor_sync(0xffffffffu, v[m], 1<<q);
    v[m] = fma2d(sp2, p, mul2d(c2, v[m]));
  }
}

// complex register gate on m-bit 1 (pair 0,1)
__device__ __forceinline__ void regCp(u64* v, const u64* G){
  u64 lo = v[0], hi = v[1];
  u64 P = fma2d(G[2], hi, mul2d(G[0], lo));
  u64 Q = fma2d(G[3], hi, mul2d(G[1], lo));
  v[0] = fixPQ(P, Q);
  P = fma2d(G[6], hi, mul2d(G[4], lo));
  Q = fma2d(G[7], hi, mul2d(G[5], lo));
  v[1] = fixPQ(P, Q);
}

// real register gate on m-bit 1
__device__ __forceinline__ void regRp(u64* v, float c, float s){
  u64 c2 = pk2(c,c), s2 = pk2(s,s), ns2 = pk2(-s,-s);
  u64 lo = v[0], hi = v[1];
  v[0] = fma2d(ns2, hi, mul2d(c2, lo));
  v[1] = fma2d(c2, hi, mul2d(s2, lo));
}

// ---------------------------------------------------------------------------
// 512 threads, 2 amps/thread, state packed (re,im) per u64.
// amp a = tid*2+m. bits: [0]=m (wire 9), [5:1]=lane (wires 8..4),
// [9:6]=warp bits (wires 3..0: amp bit 9 = warp bit 3 = wire 0).
// buffer pos(a) = ((a&1)<<9) | (a>>1); thread's own slots: (m<<9)|tid.
// Warp-bit gates: two 4-way shared combines (stage A = wires 0,1 -> amp bits
// 9,8; stage B = wires 2,3 -> amp bits 7,6). Gather fused into stage-A reads.
// ---------------------------------------------------------------------------
__global__ __launch_bounds__(TPB, 1) void qmamba_main(
    const float* __restrict__ angles,
    const float* __restrict__ poly,
    const float* __restrict__ cparams,
    const float* __restrict__ Dg,
    float* __restrict__ out)
{
  __shared__ u64 bufA[NST], bufB[NST];
  __shared__ float2 Ug[20][4];
  __shared__ u64 KpA[2][4][4][2], KpB[2][4][4][2];  // static cross coeffs
  __shared__ u64 K3A[4][4], K3B[4][4];              // per-step RY cross coeffs
  __shared__ u64 Ugp[20][2][4];                     // packed shuffle coeffs
  __shared__ u64 Urp[2][8];                         // packed reg-gate coeffs (9,19)
  __shared__ float Slo[32], Shi[32], Alo[32], Ahi[32];
  __shared__ float chs[NQ], shs[NQ], whs[NQ], fcs[NQ], fss[NQ];
  __shared__ float pcs[4], Dsh[NQ];
  __shared__ float zred[NWARP][NQ];

  const int tid = threadIdx.x;
  const int lane = tid & 31;
  const int warp = tid >> 5;          // 0..15
  const int b = blockIdx.x;

  // ---- setup ---------------------------------------------------------------
  if (tid < 20) {
    int layer = tid/10, wire = tid%10;
    int k = (layer*NQ + wire)*3;
    float al = cparams[k], be = cparams[k+1], ga = cparams[k+2];
    float sa, ca, sb, cb, sg, cg;
    sincosf(0.5f*al, &sa, &ca);
    sincosf(0.5f*be, &sb, &cb);
    sincosf(0.5f*ga, &sg, &cg);
    float2 m00 = make_float2( cb*ca,  sb*sa);
    float2 m01 = make_float2(-sb*ca, -cb*sa);
    float2 m10 = make_float2( sb*ca, -cb*sa);
    float2 m11 = make_float2( cb*ca, -sb*sa);
    float2 e0 = make_float2(cg, -sg);
    float2 e1 = make_float2(cg,  sg);
    Ug[tid][0] = cmul(e0, m00);
    Ug[tid][1] = cmul(e0, m01);
    Ug[tid][2] = cmul(e1, m10);
    Ug[tid][3] = cmul(e1, m11);
  }
  if (tid < 4) pcs[tid] = poly[tid];
  float pA = 0.f, pC = 0.f;
  if (tid < NQ) {
    Dsh[tid] = Dg[tid];
    int bi = b*SQ*NQ + tid;
    pA = angles[bi]; pC = g_C[bi];
    float dta = g_dta[bi];
    chs[tid] = 1.f; shs[tid] = 0.f;     // h=0 at step 0
    whs[tid] = dta * (0.5f*PI_F);
    float s_, c_;
    __sincosf(0.5f*pA*dta, &s_, &c_);
    fcs[tid] = c_; fss[tid] = s_;
  }
  __syncthreads();

  // static packed cross coefficients: KpA (wires 0,1), KpB (wires 2,3)
  if (tid < 128) {
    int which = tid & 1;            // 0 -> A, 1 -> B
    int part = (tid >> 1) & 1;
    int d = (tid >> 2) & 3;
    int w2 = (tid >> 4) & 3;
    int L = (tid >> 6) & 1;
    int rHi = (w2 >> 1) & 1, rLo = w2 & 1;
    int dHi = (d >> 1) & 1,  dLo = d & 1;
    int g0 = L*10 + (which ? 2 : 0);
    int g1 = L*10 + (which ? 3 : 1);
    float2 k = cmul(Ug[g0][rHi*2 + (rHi^dHi)], Ug[g1][rLo*2 + (rLo^dLo)]);
    float val = part ? k.y : k.x;
    if (which) KpB[L][w2][d][part] = pk2(val, val);
    else       KpA[L][w2][d][part] = pk2(val, val);
  }
  // static packed shuffle-gate coefficients Ugp[g][bt][c]
  if (tid < 160) {
    int g = tid >> 3;
    int bt = (tid >> 2) & 1;
    int c = tid & 3;
    float2 cs = bt ? Ug[g][3] : Ug[g][0];
    float2 cp = bt ? Ug[g][2] : Ug[g][1];
    float val = (c==0) ? cs.x : (c==1) ? cs.y : (c==2) ? cp.x : cp.y;
    Ugp[g][bt][c] = pk2(val, val);
  }
  // static packed reg-gate coeffs for gates 9 and 19 (wire 9 per layer)
  if (tid < 16) {
    int gi = tid >> 3;                  // 0 -> gate 9, 1 -> gate 19
    int gate = gi ? 19 : 9;
    int c = (tid >> 1) & 3;
    int part = tid & 1;
    float2 gv = Ug[gate][c];
    float val = part ? gv.y : gv.x;
    Urp[gi][2*c+part] = pk2(val, val);
  }

  // per-thread static: QSVT gather powers + fused-gather positions
  int rT1[AMPS], rT2[AMPS], rT3[AMPS], rT4[AMPS], posJ[AMPS];
#pragma unroll
  for (int m=0;m<AMPS;m++){
    int a = tid*AMPS + m;
    rT1[m] = gmap(a);
    rT2[m] = gmap(rT1[m]);
    rT3[m] = gmap(rT2[m]);
    rT4[m] = gmap(rT3[m]);
    int j0 = a ^ (a >> 1);
    posJ[m] = ((j0 & 1) << 9) | (j0 >> 1);
  }
  __syncthreads();

  const int w2A = warp >> 2;      // thread's (wire0,wire1) bits
  const int w2B = warp & 3;       // thread's (wire2,wire3) bits
  u64 v[AMPS];

  // ---- sequential scan -----------------------------------------------------
#pragma unroll 1
  for (int s = 0; s < SQ; ++s) {
    // prefetch next-step per-wire inputs
    float nA=0.f, nD=0.f, nC=0.f;
    if (tid < NQ && s+1 < SQ) {
      int bn = (b*SQ + s + 1)*NQ + tid;
      nA = angles[bn]; nD = g_dta[bn]; nC = g_C[bn];
    }
    // per-step split tables over 5-bit halves
    if (tid < 64) {
      int j = tid & 31;
      bool hi = tid >= 32;
      float sm = 0.f, am = 1.f;
#pragma unroll
      for (int q=0;q<5;q++){
        int w = hi ? (4-q) : (9-q);
        int bit = (j>>q)&1;
        sm += bit ? whs[w] : -whs[w];
        am *= bit ? shs[w] : chs[w];
      }
      if (hi){ Shi[j]=sm; Ahi[j]=am; } else { Slo[j]=sm; Alo[j]=am; }
    }
    // per-step final-RY packed cross coefficients (wires 0,1 -> K3A; 2,3 -> K3B)
    if (tid >= 64 && tid < 96) {
      int t = tid - 64;
      int half = t >> 4;               // 0 -> A, 1 -> B
      int w2 = (t >> 2) & 3, d = t & 3;
      int rHi = (w2>>1)&1, rLo = w2&1;
      int dHi = (d>>1)&1,  dLo = d&1;
      int wi = half ? 2 : 0;
      float f0 = dHi ? (rHi ? fss[wi]   : -fss[wi])   : fcs[wi];
      float f1 = dLo ? (rLo ? fss[wi+1] : -fss[wi+1]) : fcs[wi+1];
      float k3 = f0*f1;
      if (half) K3B[w2][d] = pk2(k3, k3);
      else      K3A[w2][d] = pk2(k3, k3);
    }
    __syncthreads();

    // init in registers: product state advanced through entire QSVT block
    {
      float p0=pcs[0], p1=pcs[1], p2=pcs[2], p3=pcs[3];
#pragma unroll
      for (int m=0;m<AMPS;m++){
        float phi = p3*(Shi[rT1[m]>>5] + Slo[rT1[m]&31])
                  + p2*(Shi[rT2[m]>>5] + Slo[rT2[m]&31])
                  + p1*(Shi[rT3[m]>>5] + Slo[rT3[m]&31])
                  + p0*(Shi[rT4[m]>>5] + Slo[rT4[m]&31]);
        float am = Ahi[rT4[m]>>5] * Alo[rT4[m]&31];
        float sp, cp; __sincosf(phi, &sp, &cp);
        v[m] = pk2(am*cp, am*sp);
      }
    }

    // ================= per-layer sections ====================================
#pragma unroll
    for (int L = 0; L < 2; ++L) {
      // ---- stage A: wires 0,1 (amp bits 9,8), gather fused for L==1 --------
#pragma unroll
      for (int m=0;m<AMPS;m++) bufA[(m<<9) + tid] = v[m];
      __syncthreads();
      {
        u64 kx[4], ky[4];
#pragma unroll
        for (int d=0; d<4; d++){ kx[d] = KpA[L][w2A][d][0]; ky[d] = KpA[L][w2A][d][1]; }
#pragma unroll
        for (int m=0;m<AMPS;m++){
          int p = L ? posJ[m] : ((m<<9) + tid);
          u64 w0 = bufA[p];
          u64 P = mul2d(kx[0], w0);
          u64 Q = mul2d(ky[0], w0);
#pragma unroll
          for (int d=1; d<4; d++){
            int msk = L ? ((d<<7) ^ (d<<6)) : (d<<7);
            u64 wd = bufA[p ^ msk];
            P = fma2d(kx[d], wd, P);
            Q = fma2d(ky[d], wd, Q);
          }
          v[m] = fixPQ(P, Q);
        }
      }
      // ---- stage B: wires 2,3 (amp bits 7,6), plain masks ------------------
#pragma unroll
      for (int m=0;m<AMPS;m++) bufB[(m<<9) + tid] = v[m];
      __syncthreads();
      {
        u64 kx[4], ky[4];
#pragma unroll
        for (int d=0; d<4; d++){ kx[d] = KpB[L][w2B][d][0]; ky[d] = KpB[L][w2B][d][1]; }
#pragma unroll
        for (int m=0;m<AMPS;m++){
          int p = (m<<9) + tid;
          u64 w0 = bufB[p];
          u64 P = mul2d(kx[0], w0);
          u64 Q = mul2d(ky[0], w0);
#pragma unroll
          for (int d=1; d<4; d++){
            u64 wd = bufB[p ^ (d<<5)];
            P = fma2d(kx[d], wd, P);
            Q = fma2d(ky[d], wd, Q);
          }
          v[m] = fixPQ(P, Q);
        }
      }
      // ---- lane shuffles: wires 4..8 ---------------------------------------
      shflCp(v, Ugp[L*10+4][(lane>>4)&1], 4);
      shflCp(v, Ugp[L*10+5][(lane>>3)&1], 3);
      shflCp(v, Ugp[L*10+6][(lane>>2)&1], 2);
      shflCp(v, Ugp[L*10+7][(lane>>1)&1], 1);
      shflCp(v, Ugp[L*10+8][lane&1], 0);
      // ---- register gate: wire 9 -------------------------------------------
      regCp(v, Urp[L]);
    }

    // ================= final RY section (gather fused) =======================
    // stage A: wires 0,1
#pragma unroll
    for (int m=0;m<AMPS;m++) bufA[(m<<9) + tid] = v[m];
    __syncthreads();
    {
      u64 k3[4];
#pragma unroll
      for (int d=0; d<4; d++) k3[d] = K3A[w2A][d];
#pragma unroll
      for (int m=0;m<AMPS;m++){
        int p = posJ[m];
        u64 acc = mul2d(k3[0], bufA[p]);
#pragma unroll
        for (int d=1; d<4; d++)
          acc = fma2d(k3[d], bufA[p ^ ((d<<7) ^ (d<<6))], acc);
        v[m] = acc;
      }
    }
    // stage B: wires 2,3
#pragma unroll
    for (int m=0;m<AMPS;m++) bufB[(m<<9) + tid] = v[m];
    __syncthreads();
    {
      u64 k3[4];
#pragma unroll
      for (int d=0; d<4; d++) k3[d] = K3B[w2B][d];
#pragma unroll
      for (int m=0;m<AMPS;m++){
        int p = (m<<9) + tid;
        u64 acc = mul2d(k3[0], bufB[p]);
#pragma unroll
        for (int d=1; d<4; d++)
          acc = fma2d(k3[d], bufB[p ^ (d<<5)], acc);
        v[m] = acc;
      }
    }
    // lane shuffles: wires 4..8 (real)
    shflRp(v, fcs[4], fss[4], 4, lane);
    shflRp(v, fcs[5], fss[5], 3, lane);
    shflRp(v, fcs[6], fss[6], 2, lane);
    shflRp(v, fcs[7], fss[7], 1, lane);
    shflRp(v, fcs[8], fss[8], 0, lane);
    // register gate: wire 9 (real)
    regRp(v, fcs[9], fss[9]);

    // ======== measurement ========
    float S, SbM;
    {
      float2 f0 = up2(v[0]), f1 = up2(v[1]);
      float pm0 = f0.x*f0.x + f0.y*f0.y;
      float pm1 = f1.x*f1.x + f1.y*f1.y;
      S = pm0 + pm1;
      SbM = pm1;                         // wire 9 (m=1)
    }
#pragma unroll
    for (int off=16; off>0; off>>=1)
      SbM += __shfl_xor_sync(0xffffffffu, SbM, off);
    // Walsh-Hadamard on S over 5 lane bits
#pragma unroll
    for (int q=16; q>0; q>>=1){
      float t = __shfl_xor_sync(0xffffffffu, S, q);
      S = ((lane & q) ? (t - S) : (S + t));
    }
    if (lane == 0){
      zred[warp][0] = (warp&8) ? -S : S;   // wire 0 = warp bit 3
      zred[warp][1] = (warp&4) ? -S : S;   // wire 1
      zred[warp][2] = (warp&2) ? -S : S;   // wire 2
      zred[warp][3] = (warp&1) ? -S : S;   // wire 3
      zred[warp][9] = S - 2.f*SbM;         // wire 9
    } else if (lane == 16) zred[warp][4] = S;
    else if (lane == 8)  zred[warp][5] = S;
    else if (lane == 4)  zred[warp][6] = S;
    else if (lane == 2)  zred[warp][7] = S;
    else if (lane == 1)  zred[warp][8] = S;
    __syncthreads();

    if (tid < NQ){
      float hn = 0.f;
#pragma unroll
      for (int w=0; w<NWARP; ++w) hn += zred[w][tid];
      int bi = (b*SQ + s)*NQ + tid;
      out[bi] = pC*hn + Dsh[tid]*pA;
      if (s+1 < SQ){
        float s_, c_;
        __sincosf(0.5f*hn, &s_, &c_);
        chs[tid] = c_; shs[tid] = s_;
        whs[tid] = nD * (0.5f*PI_F);
        __sincosf(0.5f*nA*nD, &s_, &c_);
        fcs[tid] = c_; fss[tid] = s_;
        pA = nA; pC = nC;
      }
    }
    __syncthreads();
  }
}

// ---------------------------------------------------------------------------
extern "C" void kernel_launch(void* const* d_in, const int* in_sizes, int n_in,
                              void* d_out, int out_size)
{
  const float* angles  = (const float*)d_in[0];
  const float* W_x     = (const float*)d_in[1];
  const float* W_dt    = (const float*)d_in[2];
  const float* b_dt    = (const float*)d_in[3];
  const float* poly    = (const float*)d_in[4];
  const float* cparams = (const float*)d_in[5];
  const float* D       = (const float*)d_in[6];
  float* out = (float*)d_out;

  prep_kernel<<<(BQ*SQ + 255)/256, 256>>>(angles, W_x, W_dt, b_dt);
  qmamba_main<<<BQ, TPB>>>(angles, poly, cparams, D, out);
}

// round 9
// speedup vs baseline: 1.8971x; 1.8971x over previous
#include <cuda_runtime.h>

#define BQ 128
#define SQ 512
#define NQ 10
#define NST 1024
#define TPB 256
#define AMPS 4
#define PI_F 3.14159265358979f

typedef unsigned long long u64;

// scratch (no allocations allowed)
__device__ float g_dta[BQ*SQ*NQ];
__device__ float g_C[BQ*SQ*NQ];

__device__ __forceinline__ float2 cmul(float2 a, float2 b){
  return make_float2(a.x*b.x - a.y*b.y, a.x*b.y + a.y*b.x);
}

// ---- packed f32x2 helpers (Blackwell FFMA2 via PTX); carrier = u64 ----------
__device__ __forceinline__ u64 pk2(float x, float y){
  u64 d; asm("mov.b64 %0,{%1,%2};" : "=l"(d) : "f"(x), "f"(y)); return d;
}
__device__ __forceinline__ float2 up2(u64 d){
  float2 f; asm("mov.b64 {%0,%1},%2;" : "=f"(f.x), "=f"(f.y) : "l"(d)); return f;
}
__device__ __forceinline__ u64 fma2d(u64 a, u64 b, u64 c){
  u64 r; asm("fma.rn.f32x2 %0,%1,%2,%3;" : "=l"(r) : "l"(a), "l"(b), "l"(c)); return r;
}
__device__ __forceinline__ u64 mul2d(u64 a, u64 b){
  u64 r; asm("mul.rn.f32x2 %0,%1,%2;" : "=l"(r) : "l"(a), "l"(b)); return r;
}
__device__ __forceinline__ u64 fixPQ(u64 P, u64 Q){
  float2 p = up2(P), q = up2(Q);
  return pk2(p.x - q.y, p.y + q.x);
}

// verified QSVT gather map
__device__ __forceinline__ int gmap(int a){
  int v = a;
  v ^= (v & 1) << 9;
#pragma unroll
  for (int i = 8; i >= 0; --i) v ^= ((v >> (9-i)) & 1) << (8-i);
  return v;
}

// ---------------------------------------------------------------------------
__global__ void prep_kernel(const float* __restrict__ angles,
                            const float* __restrict__ W_x,
                            const float* __restrict__ W_dt,
                            const float* __restrict__ b_dt)
{
  int idx = blockIdx.x*blockDim.x + threadIdx.x;
  if (idx >= BQ*SQ) return;
  float a[NQ];
#pragma unroll
  for (int n=0;n<NQ;n++) a[n] = angles[idx*NQ + n];
  float dtr[5];
#pragma unroll
  for (int r=0;r<5;r++){
    float s = 0.f;
#pragma unroll
    for (int n=0;n<NQ;n++) s += a[n]*W_x[r*NQ+n];
    dtr[r]=s;
  }
#pragma unroll
  for (int k=0;k<NQ;k++){
    float s=0.f;
#pragma unroll
    for (int n=0;n<NQ;n++) s += a[n]*W_x[(15+k)*NQ+n];
    g_C[idx*NQ+k]=s;
  }
#pragma unroll
  for (int n=0;n<NQ;n++){
    float s = b_dt[n];
#pragma unroll
    for (int r=0;r<5;r++) s += dtr[r]*W_dt[n*5+r];
    float sp = fmaxf(s, 0.f) + log1pf(expf(-fabsf(s)));
    g_dta[idx*NQ+n] = tanhf(sp)*PI_F;
  }
}

// complex shuffle gate on lane bit q
__device__ __forceinline__ void shflCp(u64* v, const u64* Cq, int q){
  u64 csx=Cq[0], csy=Cq[1], cpx=Cq[2], cpy=Cq[3];
#pragma unroll
  for (int m=0;m<AMPS;m++){
    u64 p = __shfl_xor_sync(0xffffffffu, v[m], 1<<q);
    u64 P = fma2d(cpx, p, mul2d(csx, v[m]));
    u64 Q = fma2d(cpy, p, mul2d(csy, v[m]));
    v[m] = fixPQ(P, Q);
  }
}

// real (RY) shuffle gate on lane bit q
__device__ __forceinline__ void shflRp(u64* v, float c, float s, int q, int lane){
  float sp = ((lane >> q) & 1) ? s : -s;
  u64 c2 = pk2(c, c), sp2 = pk2(sp, sp);
#pragma unroll
  for (int m=0;m<AMPS;m++){
    u64 p = __shfl_xor_sync(0xffffffffu, v[m], 1<<q);
    v[m] = fma2d(sp2, p, mul2d(c2, v[m]));
  }
}

// complex register gate on m-bit bm
__device__ __forceinline__ void regCp(u64* v, const u64* G, int bm){
  u64 g0x=G[0],g0y=G[1],g1x=G[2],g1y=G[3],g2x=G[4],g2y=G[5],g3x=G[6],g3y=G[7];
#pragma unroll
  for (int m=0;m<AMPS;m++){
    if (m & bm) continue;
    int mh = m | bm;
    u64 lo = v[m], hi = v[mh];
    u64 P = fma2d(g1x, hi, mul2d(g0x, lo));
    u64 Q = fma2d(g1y, hi, mul2d(g0y, lo));
    v[m]  = fixPQ(P, Q);
    P = fma2d(g3x, hi, mul2d(g2x, lo));
    Q = fma2d(g3y, hi, mul2d(g2y, lo));
    v[mh] = fixPQ(P, Q);
  }
}

// real register gate on m-bit bm
__device__ __forceinline__ void regRp(u64* v, float c, float s, int bm){
  u64 c2 = pk2(c,c), s2 = pk2(s,s), ns2 = pk2(-s,-s);
#pragma unroll
  for (int m=0;m<AMPS;m++){
    if (m & bm) continue;
    int mh = m | bm;
    u64 lo = v[m], hi = v[mh];
    v[m]  = fma2d(ns2, hi, mul2d(c2, lo));
    v[mh] = fma2d(c2, hi, mul2d(s2, lo));
  }
}

// ---------------------------------------------------------------------------
// 256 threads, 4 amps/thread, packed (re,im) per u64, NATURAL layout:
// amp a = 4*tid+m lives at slot a, split as even-pair/odd-pair ulonglong2
// arrays (bufE[t] = amps {4t,4t+1}, bufO[t] = amps {4t+2,4t+3}) so all cross
// rounds use LDS.128. Gather rounds: input quad = gray(tid)^qmask, with the
// fixed internal permutation sigma (depends on tid&1) applied at the end.
// amp bits: [1:0]=m (wires 8,9), [6:2]=lane (wires 3..7), [9:7]=warp (0,1,2).
// ---------------------------------------------------------------------------
__global__ __launch_bounds__(TPB, 1) void qmamba_main(
    const float* __restrict__ angles,
    const float* __restrict__ poly,
    const float* __restrict__ cparams,
    const float* __restrict__ Dg,
    float* __restrict__ out)
{
  __shared__ ulonglong2 bufE_A[256], bufO_A[256], bufE_B[256], bufO_B[256];
  __shared__ float2 Ug[20][4];
  __shared__ u64 Kp[2][8][8][2];   // static cross coeffs (layers), packed
  __shared__ u64 K3p[8][8];        // per-step RY cross coeffs, packed
  __shared__ u64 Ugp[20][2][4];    // packed shuffle coeffs
  __shared__ u64 Urp[4][8];        // packed reg-gate coeffs (gates 8,9,18,19)
  __shared__ float Slo[32], Shi[32], Alo[32], Ahi[32];
  __shared__ float chs[NQ], shs[NQ], fcs[NQ], fss[NQ];
  __shared__ float nAs[NQ], nDs[NQ];
  __shared__ float pcs[4], Dsh[NQ];
  __shared__ float zred[8][NQ];

  const int tid = threadIdx.x;
  const int lane = tid & 31;
  const int warp = tid >> 5;
  const int b = blockIdx.x;
  const int qg = tid ^ (tid >> 1);    // gather quad base
  const int tpar = tid & 1;           // sigma selector

  // ---- static setup --------------------------------------------------------
  if (tid < 20) {
    int layer = tid/10, wire = tid%10;
    int k = (layer*NQ + wire)*3;
    float al = cparams[k], be = cparams[k+1], ga = cparams[k+2];
    float sa, ca, sb, cb, sg, cg;
    sincosf(0.5f*al, &sa, &ca);
    sincosf(0.5f*be, &sb, &cb);
    sincosf(0.5f*ga, &sg, &cg);
    float2 m00 = make_float2( cb*ca,  sb*sa);
    float2 m01 = make_float2(-sb*ca, -cb*sa);
    float2 m10 = make_float2( sb*ca, -cb*sa);
    float2 m11 = make_float2( cb*ca, -sb*sa);
    float2 e0 = make_float2(cg, -sg);
    float2 e1 = make_float2(cg,  sg);
    Ug[tid][0] = cmul(e0, m00);
    Ug[tid][1] = cmul(e0, m01);
    Ug[tid][2] = cmul(e1, m10);
    Ug[tid][3] = cmul(e1, m11);
  }
  if (tid < 4) pcs[tid] = poly[tid];
  float pA = 0.f, pC = 0.f;
  if (tid < NQ) {
    Dsh[tid] = Dg[tid];
    int bi = b*SQ*NQ + tid;
    pA = angles[bi]; pC = g_C[bi];
    chs[tid] = 1.f; shs[tid] = 0.f;     // h=0 at step 0
    nAs[tid] = pA; nDs[tid] = g_dta[bi];
  }
  __syncthreads();

  // static packed cross coefficients Kp[L][w][d][part]
  {
    int L = tid >> 7;
    int w = (tid >> 4) & 7;
    int d = (tid >> 1) & 7;
    int part = tid & 1;
    int rA=(w>>2)&1, rB=(w>>1)&1, rC=w&1;
    int dA=(d>>2)&1, dB=(d>>1)&1, dC=d&1;
    float2 k = cmul(Ug[L*10+0][rA*2 + (rA^dA)],
               cmul(Ug[L*10+1][rB*2 + (rB^dB)],
                    Ug[L*10+2][rC*2 + (rC^dC)]));
    float val = part ? k.y : k.x;
    Kp[L][w][d][part] = pk2(val, val);
  }
  if (tid < 160) {
    int g = tid >> 3;
    int bt = (tid >> 2) & 1;
    int c = tid & 3;
    float2 cs = bt ? Ug[g][3] : Ug[g][0];
    float2 cp = bt ? Ug[g][2] : Ug[g][1];
    float val = (c==0) ? cs.x : (c==1) ? cs.y : (c==2) ? cp.x : cp.y;
    Ugp[g][bt][c] = pk2(val, val);
  }
  if (tid < 32) {
    int gi = tid >> 3;
    int gate = (gi < 2) ? (8 + gi) : (16 + gi);   // 8,9,18,19
    int c = (tid >> 1) & 3;
    int part = tid & 1;
    float2 gv = Ug[gate][c];
    float val = part ? gv.y : gv.x;
    Urp[gi][2*c+part] = pk2(val, val);
  }

  // per-thread static: QSVT gather powers
  int rT1[AMPS], rT2[AMPS], rT3[AMPS], rT4[AMPS];
#pragma unroll
  for (int m=0;m<AMPS;m++){
    int a = tid*AMPS + m;
    rT1[m] = gmap(a);
    rT2[m] = gmap(rT1[m]);
    rT3[m] = gmap(rT2[m]);
    rT4[m] = gmap(rT3[m]);
  }
  __syncthreads();

  // ---- prologue: build step-0 tables (h = 0) -------------------------------
  if (tid >= 64 && tid < 128) {          // S-tables from nDs
    int t2 = tid - 64; int j = t2 & 31; bool hi = t2 >= 32;
    float sm = 0.f;
#pragma unroll
    for (int q=0;q<5;q++){
      int w = hi ? (4-q) : (9-q);
      float wv = nDs[w]*(0.5f*PI_F);
      sm += ((j>>q)&1) ? wv : -wv;
    }
    if (hi) Shi[j]=sm; else Slo[j]=sm;
  } else if (tid >= 128 && tid < 192) {  // K3p from nAs,nDs
    int t3 = tid - 128; int w = (t3>>3)&7; int d = t3&7;
    float c0,s0,c1,s1,c2,s2;
    __sincosf(0.5f*nAs[0]*nDs[0], &s0,&c0);
    __sincosf(0.5f*nAs[1]*nDs[1], &s1,&c1);
    __sincosf(0.5f*nAs[2]*nDs[2], &s2,&c2);
    float f0 = (d&4) ? ((w&4)? s0 : -s0) : c0;
    float f1 = (d&2) ? ((w&2)? s1 : -s1) : c1;
    float f2 = (d&1) ? ((w&1)? s2 : -s2) : c2;
    float k3 = f0*f1*f2;
    K3p[w][d] = pk2(k3, k3);
  } else if (tid >= 192 && tid < 192+NQ) {  // fcs/fss
    int w = tid - 192;
    float s_, c_;
    __sincosf(0.5f*nAs[w]*nDs[w], &s_, &c_);
    fcs[w] = c_; fss[w] = s_;
  } else if (tid < 64) {                 // A-tables (h=0: chs=1, shs=0)
    int j = tid & 31; bool hi = tid >= 32;
    float am = 1.f;
#pragma unroll
    for (int q=0;q<5;q++){
      int w = hi ? (4-q) : (9-q);
      am *= ((j>>q)&1) ? shs[w] : chs[w];
    }
    if (hi) Ahi[j]=am; else Alo[j]=am;
  }
  __syncthreads();

  u64 v[AMPS];

  // ---- sequential scan -----------------------------------------------------
#pragma unroll 1
  for (int s = 0; s < SQ; ++s) {
    // prefetch next-step per-wire inputs (consumed at step end)
    float nA=0.f, nD=0.f, nC=0.f;
    if (tid < NQ && s+1 < SQ) {
      int bn = (b*SQ + s + 1)*NQ + tid;
      nA = angles[bn]; nD = g_dta[bn]; nC = g_C[bn];
    }

    // init in registers: product state advanced through entire QSVT block
    {
      float p0=pcs[0], p1=pcs[1], p2=pcs[2], p3=pcs[3];
#pragma unroll
      for (int m=0;m<AMPS;m++){
        float phi = p3*(Shi[rT1[m]>>5] + Slo[rT1[m]&31])
                  + p2*(Shi[rT2[m]>>5] + Slo[rT2[m]&31])
                  + p1*(Shi[rT3[m]>>5] + Slo[rT3[m]&31])
                  + p0*(Shi[rT4[m]>>5] + Slo[rT4[m]&31]);
        float am = Ahi[rT4[m]>>5] * Alo[rT4[m]&31];
        float sp, cp; __sincosf(phi, &sp, &cp);
        v[m] = pk2(am*cp, am*sp);
      }
    }

    // ======== section 1: layer-1 gates (no gather) ========
    bufE_A[tid] = make_ulonglong2(v[0], v[1]);
    bufO_A[tid] = make_ulonglong2(v[2], v[3]);
    __syncthreads();
    {
      u64 kx[8], ky[8];
#pragma unroll
      for (int d=0; d<8; d++){ kx[d] = Kp[0][warp][d][0]; ky[d] = Kp[0][warp][d][1]; }
      u64 P0,Q0,P1,Q1,P2,Q2,P3,Q3;
      {
        ulonglong2 e = bufE_A[tid], o = bufO_A[tid];
        P0=mul2d(kx[0],e.x); Q0=mul2d(ky[0],e.x);
        P1=mul2d(kx[0],e.y); Q1=mul2d(ky[0],e.y);
        P2=mul2d(kx[0],o.x); Q2=mul2d(ky[0],o.x);
        P3=mul2d(kx[0],o.y); Q3=mul2d(ky[0],o.y);
      }
#pragma unroll
      for (int d=1; d<8; d++){
        int qt = tid ^ (d<<5);
        ulonglong2 e = bufE_A[qt], o = bufO_A[qt];
        P0=fma2d(kx[d],e.x,P0); Q0=fma2d(ky[d],e.x,Q0);
        P1=fma2d(kx[d],e.y,P1); Q1=fma2d(ky[d],e.y,Q1);
        P2=fma2d(kx[d],o.x,P2); Q2=fma2d(ky[d],o.x,Q2);
        P3=fma2d(kx[d],o.y,P3); Q3=fma2d(ky[d],o.y,Q3);
      }
      v[0]=fixPQ(P0,Q0); v[1]=fixPQ(P1,Q1); v[2]=fixPQ(P2,Q2); v[3]=fixPQ(P3,Q3);
    }
    shflCp(v, Ugp[3][(lane>>4)&1], 4);
    shflCp(v, Ugp[4][(lane>>3)&1], 3);
    shflCp(v, Ugp[5][(lane>>2)&1], 2);
    shflCp(v, Ugp[6][(lane>>1)&1], 1);
    shflCp(v, Ugp[7][lane&1], 0);
    regCp(v, Urp[0], 2);
    regCp(v, Urp[1], 1);

    // ======== section 2: chain gather fused with layer-2 cross gate ========
    bufE_B[tid] = make_ulonglong2(v[0], v[1]);
    bufO_B[tid] = make_ulonglong2(v[2], v[3]);
    __syncthreads();
    {
      u64 kx[8], ky[8];
#pragma unroll
      for (int d=0; d<8; d++){ kx[d] = Kp[1][warp][d][0]; ky[d] = Kp[1][warp][d][1]; }
      u64 P0,Q0,P1,Q1,P2,Q2,P3,Q3;
      {
        ulonglong2 e = bufE_B[qg], o = bufO_B[qg];
        P0=mul2d(kx[0],e.x); Q0=mul2d(ky[0],e.x);
        P1=mul2d(kx[0],e.y); Q1=mul2d(ky[0],e.y);
        P2=mul2d(kx[0],o.x); Q2=mul2d(ky[0],o.x);
        P3=mul2d(kx[0],o.y); Q3=mul2d(ky[0],o.y);
      }
#pragma unroll
      for (int d=1; d<8; d++){
        int qt = qg ^ ((d<<5) ^ (d<<4));
        ulonglong2 e = bufE_B[qt], o = bufO_B[qt];
        P0=fma2d(kx[d],e.x,P0); Q0=fma2d(ky[d],e.x,Q0);
        P1=fma2d(kx[d],e.y,P1); Q1=fma2d(ky[d],e.y,Q1);
        P2=fma2d(kx[d],o.x,P2); Q2=fma2d(ky[d],o.x,Q2);
        P3=fma2d(kx[d],o.y,P3); Q3=fma2d(ky[d],o.y,Q3);
      }
      u64 o0=fixPQ(P0,Q0), o1=fixPQ(P1,Q1), o2=fixPQ(P2,Q2), o3=fixPQ(P3,Q3);
      if (tpar){ v[0]=o2; v[1]=o3; v[2]=o1; v[3]=o0; }
      else     { v[0]=o0; v[1]=o1; v[2]=o3; v[3]=o2; }
    }
    shflCp(v, Ugp[13][(lane>>4)&1], 4);
    shflCp(v, Ugp[14][(lane>>3)&1], 3);
    shflCp(v, Ugp[15][(lane>>2)&1], 2);
    shflCp(v, Ugp[16][(lane>>1)&1], 1);
    shflCp(v, Ugp[17][lane&1], 0);
    regCp(v, Urp[2], 2);
    regCp(v, Urp[3], 1);

    // ======== section 3: chain gather fused with final-RY cross gate ========
    bufE_A[tid] = make_ulonglong2(v[0], v[1]);
    bufO_A[tid] = make_ulonglong2(v[2], v[3]);
    __syncthreads();
    {
      u64 k3[8];
#pragma unroll
      for (int d=0; d<8; d++) k3[d] = K3p[warp][d];
      u64 A0,A1,A2,A3;
      {
        ulonglong2 e = bufE_A[qg], o = bufO_A[qg];
        A0=mul2d(k3[0],e.x); A1=mul2d(k3[0],e.y);
        A2=mul2d(k3[0],o.x); A3=mul2d(k3[0],o.y);
      }
#pragma unroll
      for (int d=1; d<8; d++){
        int qt = qg ^ ((d<<5) ^ (d<<4));
        ulonglong2 e = bufE_A[qt], o = bufO_A[qt];
        A0=fma2d(k3[d],e.x,A0); A1=fma2d(k3[d],e.y,A1);
        A2=fma2d(k3[d],o.x,A2); A3=fma2d(k3[d],o.y,A3);
      }
      if (tpar){ v[0]=A2; v[1]=A3; v[2]=A1; v[3]=A0; }
      else     { v[0]=A0; v[1]=A1; v[2]=A3; v[3]=A2; }
    }
    shflRp(v, fcs[3], fss[3], 4, lane);
    shflRp(v, fcs[4], fss[4], 3, lane);
    shflRp(v, fcs[5], fss[5], 2, lane);
    shflRp(v, fcs[6], fss[6], 1, lane);
    shflRp(v, fcs[7], fss[7], 0, lane);
    regRp(v, fcs[8], fss[8], 2);
    regRp(v, fcs[9], fss[9], 1);

    // ======== measurement ========
    float S=0.f, SbH=0.f, SbL=0.f;
#pragma unroll
    for (int m=0;m<AMPS;m++){
      float2 f = up2(v[m]);
      float pm = f.x*f.x + f.y*f.y;
      S += pm;
      if (m & 2) SbH += pm;   // wire 8
      if (m & 1) SbL += pm;   // wire 9
    }
#pragma unroll
    for (int off=16; off>0; off>>=1){
      SbH += __shfl_xor_sync(0xffffffffu, SbH, off);
      SbL += __shfl_xor_sync(0xffffffffu, SbL, off);
    }
#pragma unroll
    for (int q=16; q>0; q>>=1){
      float t = __shfl_xor_sync(0xffffffffu, S, q);
      S = ((lane & q) ? (t - S) : (S + t));
    }
    // publish next-step wire inputs (prefetched at loop top)
    if (tid < NQ) { nAs[tid] = nA; nDs[tid] = nD; }
    if (lane == 0){
      zred[warp][0] = (warp&4) ? -S : S;
      zred[warp][1] = (warp&2) ? -S : S;
      zred[warp][2] = (warp&1) ? -S : S;
      zred[warp][8] = S - 2.f*SbH;
      zred[warp][9] = S - 2.f*SbL;
    } else if (lane == 16) zred[warp][3] = S;
    else if (lane == 8)  zred[warp][4] = S;
    else if (lane == 4)  zred[warp][5] = S;
    else if (lane == 2)  zred[warp][6] = S;
    else if (lane == 1)  zred[warp][7] = S;
    __syncthreads();

    // ======== parallel inter-step segment ========
    if (tid < NQ){
      float hn = zred[0][tid] + zred[1][tid] + zred[2][tid] + zred[3][tid]
               + zred[4][tid] + zred[5][tid] + zred[6][tid] + zred[7][tid];
      int bi = (b*SQ + s)*NQ + tid;
      out[bi] = pC*hn + Dsh[tid]*pA;
      float s_, c_;
      __sincosf(0.5f*hn, &s_, &c_);
      chs[tid] = c_; shs[tid] = s_;
      pA = nA; pC = nC;
    } else if (tid >= 64 && tid < 128) {   // S-tables for next step (dta only)
      int t2 = tid - 64; int j = t2 & 31; bool hi = t2 >= 32;
      float sm = 0.f;
#pragma unroll
      for (int q=0;q<5;q++){
        int w = hi ? (4-q) : (9-q);
        float wv = nDs[w]*(0.5f*PI_F);
        sm += ((j>>q)&1) ? wv : -wv;
      }
      if (hi) Shi[j]=sm; else Slo[j]=sm;
    } else if (tid >= 128 && tid < 192) {  // K3p for next step (x*dta only)
      int t3 = tid - 128; int w = (t3>>3)&7; int d = t3&7;
      float c0,s0,c1,s1,c2,s2;
      __sincosf(0.5f*nAs[0]*nDs[0], &s0,&c0);
      __sincosf(0.5f*nAs[1]*nDs[1], &s1,&c1);
      __sincosf(0.5f*nAs[2]*nDs[2], &s2,&c2);
      float f0 = (d&4) ? ((w&4)? s0 : -s0) : c0;
      float f1 = (d&2) ? ((w&2)? s1 : -s1) : c1;
      float f2 = (d&1) ? ((w&1)? s2 : -s2) : c2;
      float k3 = f0*f1*f2;
      K3p[w][d] = pk2(k3, k3);
    } else if (tid >= 192 && tid < 192+NQ) {  // fcs/fss for next step
      int w = tid - 192;
      float s_, c_;
      __sincosf(0.5f*nAs[w]*nDs[w], &s_, &c_);
      fcs[w] = c_; fss[w] = s_;
    }
    __syncthreads();
    // A-tables need fresh chs/shs
    if (tid < 64) {
      int j = tid & 31; bool hi = tid >= 32;
      float am = 1.f;
#pragma unroll
      for (int q=0;q<5;q++){
        int w = hi ? (4-q) : (9-q);
        am *= ((j>>q)&1) ? shs[w] : chs[w];
      }
      if (hi) Ahi[j]=am; else Alo[j]=am;
    }
    __syncthreads();
  }
}

// ---------------------------------------------------------------------------
extern "C" void kernel_launch(void* const* d_in, const int* in_sizes, int n_in,
                              void* d_out, int out_size)
{
  const float* angles  = (const float*)d_in[0];
  const float* W_x     = (const float*)d_in[1];
  const float* W_dt    = (const float*)d_in[2];
  const float* b_dt    = (const float*)d_in[3];
  const float* poly    = (const float*)d_in[4];
  const float* cparams = (const float*)d_in[5];
  const float* D       = (const float*)d_in[6];
  float* out = (float*)d_out;

  prep_kernel<<<(BQ*SQ + 255)/256, 256>>>(angles, W_x, W_dt, b_dt);
  qmamba_main<<<BQ, TPB>>>(angles, poly, cparams, D, out);
}

// round 10
// speedup vs baseline: 1.9149x; 1.0093x over previous
#include <cuda_runtime.h>

#define BQ 128
#define SQ 512
#define NQ 10
#define NST 1024
#define TPB 256
#define AMPS 4
#define PI_F 3.14159265358979f

typedef unsigned long long u64;

// scratch (no allocations allowed)
__device__ float g_dta[BQ*SQ*NQ];
__device__ float g_C[BQ*SQ*NQ];

__device__ __forceinline__ float2 cmul(float2 a, float2 b){
  return make_float2(a.x*b.x - a.y*b.y, a.x*b.y + a.y*b.x);
}

// ---- packed f32x2 helpers (Blackwell FFMA2 via PTX); carrier = u64 ----------
__device__ __forceinline__ u64 pk2(float x, float y){
  u64 d; asm("mov.b64 %0,{%1,%2};" : "=l"(d) : "f"(x), "f"(y)); return d;
}
__device__ __forceinline__ float2 up2(u64 d){
  float2 f; asm("mov.b64 {%0,%1},%2;" : "=f"(f.x), "=f"(f.y) : "l"(d)); return f;
}
__device__ __forceinline__ u64 fma2d(u64 a, u64 b, u64 c){
  u64 r; asm("fma.rn.f32x2 %0,%1,%2,%3;" : "=l"(r) : "l"(a), "l"(b), "l"(c)); return r;
}
__device__ __forceinline__ u64 mul2d(u64 a, u64 b){
  u64 r; asm("mul.rn.f32x2 %0,%1,%2;" : "=l"(r) : "l"(a), "l"(b)); return r;
}
__device__ __forceinline__ u64 add2d(u64 a, u64 b){
  u64 r; asm("add.rn.f32x2 %0,%1,%2;" : "=l"(r) : "l"(a), "l"(b)); return r;
}
__device__ __forceinline__ u64 fixPQ(u64 P, u64 Q){
  float2 p = up2(P), q = up2(Q);
  return pk2(p.x - q.y, p.y + q.x);
}

// verified QSVT gather map
__device__ __forceinline__ int gmap(int a){
  int v = a;
  v ^= (v & 1) << 9;
#pragma unroll
  for (int i = 8; i >= 0; --i) v ^= ((v >> (9-i)) & 1) << (8-i);
  return v;
}

// ---------------------------------------------------------------------------
__global__ void prep_kernel(const float* __restrict__ angles,
                            const float* __restrict__ W_x,
                            const float* __restrict__ W_dt,
                            const float* __restrict__ b_dt)
{
  int idx = blockIdx.x*blockDim.x + threadIdx.x;
  if (idx >= BQ*SQ) return;
  float a[NQ];
#pragma unroll
  for (int n=0;n<NQ;n++) a[n] = angles[idx*NQ + n];
  float dtr[5];
#pragma unroll
  for (int r=0;r<5;r++){
    float s = 0.f;
#pragma unroll
    for (int n=0;n<NQ;n++) s += a[n]*W_x[r*NQ+n];
    dtr[r]=s;
  }
#pragma unroll
  for (int k=0;k<NQ;k++){
    float s=0.f;
#pragma unroll
    for (int n=0;n<NQ;n++) s += a[n]*W_x[(15+k)*NQ+n];
    g_C[idx*NQ+k]=s;
  }
#pragma unroll
  for (int n=0;n<NQ;n++){
    float s = b_dt[n];
#pragma unroll
    for (int r=0;r<5;r++) s += dtr[r]*W_dt[n*5+r];
    float sp = fmaxf(s, 0.f) + log1pf(expf(-fabsf(s)));
    g_dta[idx*NQ+n] = tanhf(sp)*PI_F;
  }
}

// single complex shuffle gate on lane bit q
__device__ __forceinline__ void shflCp(u64* v, const u64* Cq, int q){
  u64 csx=Cq[0], csy=Cq[1], cpx=Cq[2], cpy=Cq[3];
#pragma unroll
  for (int m=0;m<AMPS;m++){
    u64 p = __shfl_xor_sync(0xffffffffu, v[m], 1<<q);
    u64 P = fma2d(cpx, p, mul2d(csx, v[m]));
    u64 Q = fma2d(cpy, p, mul2d(csy, v[m]));
    v[m] = fixPQ(P, Q);
  }
}

// paired complex shuffle gates on lane bits qa>qb (one 4-way combine)
// K = &K2s[L][pr][own][0][0]: 8 u64 = [d][part], d = dA*2+dB
__device__ __forceinline__ void shflC2(u64* v, const u64* K, int qa, int qb){
  u64 k0x=K[0],k0y=K[1],k1x=K[2],k1y=K[3],k2x=K[4],k2y=K[5],k3x=K[6],k3y=K[7];
#pragma unroll
  for (int m=0;m<AMPS;m++){
    u64 o = v[m];
    u64 p2 = __shfl_xor_sync(0xffffffffu, o, 1<<qb);          // d=(0,1)
    u64 p1 = __shfl_xor_sync(0xffffffffu, o, 1<<qa);          // d=(1,0)
    u64 p3 = __shfl_xor_sync(0xffffffffu, o, (1<<qa)|(1<<qb));// d=(1,1)
    u64 P = mul2d(k0x, o),  Q = mul2d(k0y, o);
    P = fma2d(k1x, p2, P);  Q = fma2d(k1y, p2, Q);
    P = fma2d(k2x, p1, P);  Q = fma2d(k2y, p1, Q);
    P = fma2d(k3x, p3, P);  Q = fma2d(k3y, p3, Q);
    v[m] = fixPQ(P, Q);
  }
}

// single real (RY) shuffle gate on lane bit q
__device__ __forceinline__ void shflRp(u64* v, float c, float s, int q, int lane){
  float sp = ((lane >> q) & 1) ? s : -s;
  u64 c2 = pk2(c, c), sp2 = pk2(sp, sp);
#pragma unroll
  for (int m=0;m<AMPS;m++){
    u64 p = __shfl_xor_sync(0xffffffffu, v[m], 1<<q);
    v[m] = fma2d(sp2, p, mul2d(c2, v[m]));
  }
}

// paired real (RY) shuffle gates on lane bits qa>qb
__device__ __forceinline__ void shflR2(u64* v, float cA, float sA, float cB, float sB,
                                       int qa, int qb, int lane){
  float tA = ((lane >> qa) & 1) ? sA : -sA;
  float tB = ((lane >> qb) & 1) ? sB : -sB;
  float c00 = cA*cB, c01 = cA*tB, c10 = tA*cB, c11 = tA*tB;
  u64 k0 = pk2(c00,c00), k1 = pk2(c01,c01), k2 = pk2(c10,c10), k3 = pk2(c11,c11);
#pragma unroll
  for (int m=0;m<AMPS;m++){
    u64 o = v[m];
    u64 p2 = __shfl_xor_sync(0xffffffffu, o, 1<<qb);
    u64 p1 = __shfl_xor_sync(0xffffffffu, o, 1<<qa);
    u64 p3 = __shfl_xor_sync(0xffffffffu, o, (1<<qa)|(1<<qb));
    u64 acc = mul2d(k0, o);
    acc = fma2d(k1, p2, acc);
    acc = fma2d(k2, p1, acc);
    acc = fma2d(k3, p3, acc);
    v[m] = acc;
  }
}

// complex register gate on m-bit bm
__device__ __forceinline__ void regCp(u64* v, const u64* G, int bm){
  u64 g0x=G[0],g0y=G[1],g1x=G[2],g1y=G[3],g2x=G[4],g2y=G[5],g3x=G[6],g3y=G[7];
#pragma unroll
  for (int m=0;m<AMPS;m++){
    if (m & bm) continue;
    int mh = m | bm;
    u64 lo = v[m], hi = v[mh];
    u64 P = fma2d(g1x, hi, mul2d(g0x, lo));
    u64 Q = fma2d(g1y, hi, mul2d(g0y, lo));
    v[m]  = fixPQ(P, Q);
    P = fma2d(g3x, hi, mul2d(g2x, lo));
    Q = fma2d(g3y, hi, mul2d(g2y, lo));
    v[mh] = fixPQ(P, Q);
  }
}

// real register gate on m-bit bm
__device__ __forceinline__ void regRp(u64* v, float c, float s, int bm){
  u64 c2 = pk2(c,c), s2 = pk2(s,s), ns2 = pk2(-s,-s);
#pragma unroll
  for (int m=0;m<AMPS;m++){
    if (m & bm) continue;
    int mh = m | bm;
    u64 lo = v[m], hi = v[mh];
    v[m]  = fma2d(ns2, hi, mul2d(c2, lo));
    v[mh] = fma2d(c2, hi, mul2d(s2, lo));
  }
}

// ---------------------------------------------------------------------------
// 256 threads, 4 amps/thread, state packed (re,im) per u64.
// amp a = tid*4+m. bits: [1:0]=m (wires 8,9), [6:2]=lane (wires 3..7),
// [9:7]=warp (wires 0,1,2). pos(a) = (a&3)*256 + (a>>2).
// Lane-bit gates applied as paired 4-way shuffle combines (depth 5 -> 3).
// ---------------------------------------------------------------------------
__global__ __launch_bounds__(TPB, 1) void qmamba_main(
    const float* __restrict__ angles,
    const float* __restrict__ poly,
    const float* __restrict__ cparams,
    const float* __restrict__ Dg,
    float* __restrict__ out)
{
  __shared__ u64 bufA[NST], bufB[NST];
  __shared__ float2 Ug[20][4];
  __shared__ u64 Kp[2][8][8][2];     // static cross coeffs, packed
  __shared__ u64 K2s[2][2][4][4][2]; // static paired lane-gate coeffs
  __shared__ u64 K3p[8][8];          // per-step RY cross coeffs, packed
  __shared__ u64 Ugp[20][2][4];      // packed single-gate shuffle coeffs
  __shared__ u64 Urp[4][8];          // packed reg-gate coeffs (gates 8,9,18,19)
  __shared__ float Slo[32], Shi[32], Alo[32], Ahi[32];
  __shared__ float chs[NQ], shs[NQ], whs[NQ], fcs[NQ], fss[NQ];
  __shared__ float pcs[4], Dsh[NQ];
  __shared__ float zred[8][NQ];

  const int tid = threadIdx.x;
  const int lane = tid & 31;
  const int warp = tid >> 5;
  const int b = blockIdx.x;
  const int ownA = (((lane>>4)&1)<<1) | ((lane>>3)&1);   // bits 4,3
  const int ownB = (((lane>>2)&1)<<1) | ((lane>>1)&1);   // bits 2,1

  // ---- setup ---------------------------------------------------------------
  if (tid < 20) {
    int layer = tid/10, wire = tid%10;
    int k = (layer*NQ + wire)*3;
    float al = cparams[k], be = cparams[k+1], ga = cparams[k+2];
    float sa, ca, sb, cb, sg, cg;
    sincosf(0.5f*al, &sa, &ca);
    sincosf(0.5f*be, &sb, &cb);
    sincosf(0.5f*ga, &sg, &cg);
    float2 m00 = make_float2( cb*ca,  sb*sa);
    float2 m01 = make_float2(-sb*ca, -cb*sa);
    float2 m10 = make_float2( sb*ca, -cb*sa);
    float2 m11 = make_float2( cb*ca, -sb*sa);
    float2 e0 = make_float2(cg, -sg);
    float2 e1 = make_float2(cg,  sg);
    Ug[tid][0] = cmul(e0, m00);
    Ug[tid][1] = cmul(e0, m01);
    Ug[tid][2] = cmul(e1, m10);
    Ug[tid][3] = cmul(e1, m11);
  }
  if (tid < 4) pcs[tid] = poly[tid];
  float pA = 0.f, pC = 0.f;
  if (tid < NQ) {
    Dsh[tid] = Dg[tid];
    int bi = b*SQ*NQ + tid;
    pA = angles[bi]; pC = g_C[bi];
    float dta = g_dta[bi];
    chs[tid] = 1.f; shs[tid] = 0.f;     // h=0 at step 0
    whs[tid] = dta * (0.5f*PI_F);
    float s_, c_;
    __sincosf(0.5f*pA*dta, &s_, &c_);
    fcs[tid] = c_; fss[tid] = s_;
  }
  __syncthreads();

  // static packed cross coefficients Kp[L][w][d][part]
  {
    int L = tid >> 7;
    int w = (tid >> 4) & 7;
    int d = (tid >> 1) & 7;
    int part = tid & 1;
    int rA=(w>>2)&1, rB=(w>>1)&1, rC=w&1;
    int dA=(d>>2)&1, dB=(d>>1)&1, dC=d&1;
    float2 k = cmul(Ug[L*10+0][rA*2 + (rA^dA)],
               cmul(Ug[L*10+1][rB*2 + (rB^dB)],
                    Ug[L*10+2][rC*2 + (rC^dC)]));
    float val = part ? k.y : k.x;
    Kp[L][w][d][part] = pk2(val, val);
  }
  // static paired lane-gate coefficients K2s[L][pr][own][d][part]
  if (tid < 128) {
    int L = (tid >> 6) & 1;
    int pr = (tid >> 5) & 1;
    int own = (tid >> 3) & 3;
    int d = (tid >> 1) & 3;
    int part = tid & 1;
    int a = own >> 1, bb = own & 1;
    int dA = d >> 1, dB = d & 1;
    int gA = L*10 + 3 + pr*2, gB = gA + 1;
    float2 k = cmul(Ug[gA][a*2 + (a^dA)], Ug[gB][bb*2 + (bb^dB)]);
    float val = part ? k.y : k.x;
    K2s[L][pr][own][d][part] = pk2(val, val);
  }
  // static packed single-gate shuffle coefficients Ugp[g][bt][c]
  if (tid < 160) {
    int g = tid >> 3;
    int bt = (tid >> 2) & 1;
    int c = tid & 3;
    float2 cs = bt ? Ug[g][3] : Ug[g][0];
    float2 cp = bt ? Ug[g][2] : Ug[g][1];
    float val = (c==0) ? cs.x : (c==1) ? cs.y : (c==2) ? cp.x : cp.y;
    Ugp[g][bt][c] = pk2(val, val);
  }
  // static packed reg-gate coefficients Urp for gates 8,9,18,19
  if (tid < 32) {
    int gi = tid >> 3;
    int gate = (gi < 2) ? (8 + gi) : (16 + gi);   // 8,9,18,19
    int c = (tid >> 1) & 3;
    int part = tid & 1;
    float2 gv = Ug[gate][c];
    float val = part ? gv.y : gv.x;
    Urp[gi][2*c+part] = pk2(val, val);
  }

  // per-thread static: QSVT gather powers + fused-gather positions
  int rT1[AMPS], rT2[AMPS], rT3[AMPS], rT4[AMPS], posJ[AMPS];
#pragma unroll
  for (int m=0;m<AMPS;m++){
    int a = tid*AMPS + m;
    rT1[m] = gmap(a);
    rT2[m] = gmap(rT1[m]);
    rT3[m] = gmap(rT2[m]);
    rT4[m] = gmap(rT3[m]);
    int j0 = a ^ (a >> 1);
    posJ[m] = ((j0 & 3) << 8) | (j0 >> 2);
  }
  __syncthreads();

  u64 v[AMPS];

  // ---- sequential scan -----------------------------------------------------
#pragma unroll 1
  for (int s = 0; s < SQ; ++s) {
    // prefetch next-step per-wire inputs
    float nA=0.f, nD=0.f, nC=0.f;
    if (tid < NQ && s+1 < SQ) {
      int bn = (b*SQ + s + 1)*NQ + tid;
      nA = angles[bn]; nD = g_dta[bn]; nC = g_C[bn];
    }
    // per-step split tables over 5-bit halves
    if (tid < 64) {
      int j = tid & 31;
      bool hi = tid >= 32;
      float sm = 0.f, am = 1.f;
#pragma unroll
      for (int q=0;q<5;q++){
        int w = hi ? (4-q) : (9-q);
        int bit = (j>>q)&1;
        sm += bit ? whs[w] : -whs[w];
        am *= bit ? shs[w] : chs[w];
      }
      if (hi){ Shi[j]=sm; Ahi[j]=am; } else { Slo[j]=sm; Alo[j]=am; }
    }
    // per-step final-RY packed cross coefficients (wires 0,1,2)
    if (tid >= 64 && tid < 128) {
      int t = tid - 64;
      int w = t >> 3, d = t & 7;
      float f0 = (d&4) ? ((w&4) ? fss[0] : -fss[0]) : fcs[0];
      float f1 = (d&2) ? ((w&2) ? fss[1] : -fss[1]) : fcs[1];
      float f2 = (d&1) ? ((w&1) ? fss[2] : -fss[2]) : fcs[2];
      float k3 = f0*f1*f2;
      K3p[w][d] = pk2(k3, k3);
    }
    __syncthreads();

    // init in registers: product state advanced through entire QSVT block
    {
      float p0=pcs[0], p1=pcs[1], p2=pcs[2], p3=pcs[3];
#pragma unroll
      for (int m=0;m<AMPS;m++){
        float phi = p3*(Shi[rT1[m]>>5] + Slo[rT1[m]&31])
                  + p2*(Shi[rT2[m]>>5] + Slo[rT2[m]&31])
                  + p1*(Shi[rT3[m]>>5] + Slo[rT3[m]&31])
                  + p0*(Shi[rT4[m]>>5] + Slo[rT4[m]&31]);
        float am = Ahi[rT4[m]>>5] * Alo[rT4[m]&31];
        float sp, cp; __sincosf(phi, &sp, &cp);
        v[m] = pk2(am*cp, am*sp);
      }
    }

    // ======== section 1: layer-1 gates ========
#pragma unroll
    for (int m=0;m<AMPS;m++) bufA[(m<<8) + tid] = v[m];
    __syncthreads();
    {
      u64 kx[8], ky[8];
#pragma unroll
      for (int d=0; d<8; d++){ kx[d] = Kp[0][warp][d][0]; ky[d] = Kp[0][warp][d][1]; }
#pragma unroll
      for (int m=0;m<AMPS;m++){
        int p = (m<<8) + tid;
        u64 w0 = bufA[p];
        u64 P = mul2d(kx[0], w0);
        u64 Q = mul2d(ky[0], w0);
#pragma unroll
        for (int d=1; d<8; d++){
          u64 wd = bufA[p ^ (d<<5)];
          P = fma2d(kx[d], wd, P);
          Q = fma2d(ky[d], wd, Q);
        }
        v[m] = fixPQ(P, Q);
      }
    }
    shflC2(v, &K2s[0][0][ownA][0][0], 4, 3);
    shflC2(v, &K2s[0][1][ownB][0][0], 2, 1);
    shflCp(v, Ugp[7][lane&1], 0);
    regCp(v, Urp[0], 2);
    regCp(v, Urp[1], 1);

    // ======== section 2: chain gather fused with layer-2 cross gate ========
#pragma unroll
    for (int m=0;m<AMPS;m++) bufB[(m<<8) + tid] = v[m];
    __syncthreads();
    {
      u64 kx[8], ky[8];
#pragma unroll
      for (int d=0; d<8; d++){ kx[d] = Kp[1][warp][d][0]; ky[d] = Kp[1][warp][d][1]; }
#pragma unroll
      for (int m=0;m<AMPS;m++){
        int p = posJ[m];
        u64 w0 = bufB[p];
        u64 P = mul2d(kx[0], w0);
        u64 Q = mul2d(ky[0], w0);
#pragma unroll
        for (int d=1; d<8; d++){
          u64 wd = bufB[p ^ ((d<<5) ^ (d<<4))];
          P = fma2d(kx[d], wd, P);
          Q = fma2d(ky[d], wd, Q);
        }
        v[m] = fixPQ(P, Q);
      }
    }
    shflC2(v, &K2s[1][0][ownA][0][0], 4, 3);
    shflC2(v, &K2s[1][1][ownB][0][0], 2, 1);
    shflCp(v, Ugp[17][lane&1], 0);
    regCp(v, Urp[2], 2);
    regCp(v, Urp[3], 1);

    // ======== section 3: chain gather fused with final-RY cross gate ========
#pragma unroll
    for (int m=0;m<AMPS;m++) bufA[(m<<8) + tid] = v[m];
    __syncthreads();
    {
      u64 k3[8];
#pragma unroll
      for (int d=0; d<8; d++) k3[d] = K3p[warp][d];
#pragma unroll
      for (int m=0;m<AMPS;m++){
        int p = posJ[m];
        u64 acc = mul2d(k3[0], bufA[p]);
#pragma unroll
        for (int d=1; d<8; d++){
          u64 wd = bufA[p ^ ((d<<5) ^ (d<<4))];
          acc = fma2d(k3[d], wd, acc);
        }
        v[m] = acc;
      }
    }
    shflR2(v, fcs[3], fss[3], fcs[4], fss[4], 4, 3, lane);
    shflR2(v, fcs[5], fss[5], fcs[6], fss[6], 2, 1, lane);
    shflRp(v, fcs[7], fss[7], 0, lane);
    regRp(v, fcs[8], fss[8], 2);
    regRp(v, fcs[9], fss[9], 1);

    // ======== measurement ========
    float S=0.f, SbH=0.f, SbL=0.f;
#pragma unroll
    for (int m=0;m<AMPS;m++){
      float2 f = up2(v[m]);
      float pm = f.x*f.x + f.y*f.y;
      S += pm;
      if (m & 2) SbH += pm;   // wire 8
      if (m & 1) SbL += pm;   // wire 9
    }
    // packed reduce of (SbH, SbL)
    {
      u64 Sb = pk2(SbH, SbL);
#pragma unroll
      for (int off=16; off>0; off>>=1)
        Sb = add2d(Sb, __shfl_xor_sync(0xffffffffu, Sb, off));
      float2 f = up2(Sb);
      SbH = f.x; SbL = f.y;
    }
    // Walsh-Hadamard on S over 5 lane bits
#pragma unroll
    for (int q=16; q>0; q>>=1){
      float t = __shfl_xor_sync(0xffffffffu, S, q);
      S = ((lane & q) ? (t - S) : (S + t));
    }
    if (lane == 0){
      zred[warp][0] = (warp&4) ? -S : S;
      zred[warp][1] = (warp&2) ? -S : S;
      zred[warp][2] = (warp&1) ? -S : S;
      zred[warp][8] = S - 2.f*SbH;
      zred[warp][9] = S - 2.f*SbL;
    } else if (lane == 16) zred[warp][3] = S;
    else if (lane == 8)  zred[warp][4] = S;
    else if (lane == 4)  zred[warp][5] = S;
    else if (lane == 2)  zred[warp][6] = S;
    else if (lane == 1)  zred[warp][7] = S;
    __syncthreads();

    if (tid < NQ){
      float hn = zred[0][tid] + zred[1][tid] + zred[2][tid] + zred[3][tid]
               + zred[4][tid] + zred[5][tid] + zred[6][tid] + zred[7][tid];
      int bi = (b*SQ + s)*NQ + tid;
      out[bi] = pC*hn + Dsh[tid]*pA;
      if (s+1 < SQ){
        float s_, c_;
        __sincosf(0.5f*hn, &s_, &c_);
        chs[tid] = c_; shs[tid] = s_;
        whs[tid] = nD * (0.5f*PI_F);
        __sincosf(0.5f*nA*nD, &s_, &c_);
        fcs[tid] = c_; fss[tid] = s_;
        pA = nA; pC = nC;
      }
    }
    __syncthreads();
  }
}

// ---------------------------------------------------------------------------
extern "C" void kernel_launch(void* const* d_in, const int* in_sizes, int n_in,
                              void* d_out, int out_size)
{
  const float* angles  = (const float*)d_in[0];
  const float* W_x     = (const float*)d_in[1];
  const float* W_dt    = (const float*)d_in[2];
  const float* b_dt    = (const float*)d_in[3];
  const float* poly    = (const float*)d_in[4];
  const float* cparams = (const float*)d_in[5];
  const float* D       = (const float*)d_in[6];
  float* out = (float*)d_out;

  prep_kernel<<<(BQ*SQ + 255)/256, 256>>>(angles, W_x, W_dt, b_dt);
  qmamba_main<<<BQ, TPB>>>(angles, poly, cparams, D, out);
}